// round 1
// baseline (speedup 1.0000x reference)
#include <cuda_runtime.h>
#include <cuda_bf16.h>
#include <cstdint>

// Problem constants
#define BB 2
#define TT 2048
#define DD 1024
#define HH 16
#define WW 16
#define EE 8
#define HDIM 64
#define MM (BB*TT)          // 4096 rows

// ---------------- scratch (static device arrays; no allocation) ----------------
__device__ float g_xt[MM*DD];          // tf32-rounded x
__device__ float g_wq[WW*DD*DD];       // q_w transposed to [w][i][o], rounded
__device__ float g_wk[WW*DD*DD];
__device__ float g_wv[DD*DD];          // v_w transposed to [d][o], rounded
__device__ float g_wp[DD*DD];
__device__ float g_q[MM*DD];
__device__ float g_k[MM*DD];
__device__ float g_v[MM*DD];
__device__ float g_out[MM*DD];         // attention output (rounded for p-GEMM)
__device__ float g_s[BB*HH*EE*TT];     // log-shift scores -> alphas

__device__ __forceinline__ float rna_tf32(float x) {
    unsigned r;
    asm("cvt.rna.tf32.f32 %0, %1;" : "=r"(r) : "f"(x));
    return __uint_as_float(r);
}

// ---------------- prep kernels ----------------
__global__ void round_copy_kernel(const float* __restrict__ in, float* __restrict__ out, int n4) {
    int i = blockIdx.x * blockDim.x + threadIdx.x;
    if (i < n4) {
        float4 v = ((const float4*)in)[i];
        v.x = rna_tf32(v.x); v.y = rna_tf32(v.y);
        v.z = rna_tf32(v.z); v.w = rna_tf32(v.w);
        ((float4*)out)[i] = v;
    }
}

// q_w[o][i][w] -> wt[(w*D + i)*D + o], rounded.  block (32,8), grid (32,128)
__global__ void transpose_conv_w_kernel(const float* __restrict__ w, float* __restrict__ wt) {
    int o = blockIdx.x * 32 + threadIdx.x;
    int i = blockIdx.y * 8 + threadIdx.y;
    const float4* src = (const float4*)(w + ((size_t)o * DD + i) * WW);
    float vals[16];
    #pragma unroll
    for (int p = 0; p < 4; p++) {
        float4 v = src[p];
        vals[p*4+0] = v.x; vals[p*4+1] = v.y; vals[p*4+2] = v.z; vals[p*4+3] = v.w;
    }
    #pragma unroll
    for (int wi = 0; wi < WW; wi++)
        wt[((size_t)wi * DD + i) * DD + o] = rna_tf32(vals[wi]);
}

// w[o][d] -> wt[d][o], rounded.  block (32,8), grid (32,32)
__global__ void transpose_dense_kernel(const float* __restrict__ w, float* __restrict__ wt) {
    __shared__ float tile[32][33];
    int x = blockIdx.x * 32 + threadIdx.x;   // d (input col)
    int y0 = blockIdx.y * 32;                // o
    #pragma unroll
    for (int j = 0; j < 32; j += 8)
        tile[threadIdx.y + j][threadIdx.x] = rna_tf32(w[(size_t)(y0 + threadIdx.y + j) * DD + x]);
    __syncthreads();
    int xo = blockIdx.y * 32 + threadIdx.x;  // o (output col)
    int yo0 = blockIdx.x * 32;               // d
    #pragma unroll
    for (int j = 0; j < 32; j += 8)
        wt[(size_t)(yo0 + threadIdx.y + j) * DD + xo] = tile[threadIdx.x][threadIdx.y + j];
}

// ---------------- tf32 tensor-core GEMM (handles conv taps) ----------------
// C[M=4096, N=1024] = A_shifted @ Bw + bias.  K = taps*1024, K-chunk w gives row
// offset (w - (taps-1)) into A (zero-padded above batch start).
#define Bb_M 128
#define Bb_N 128
#define Bb_K 32

__global__ __launch_bounds__(256, 1)
void gemm_tf32_kernel(const float* __restrict__ A, const float* __restrict__ Bw,
                      const float* __restrict__ bias, float* __restrict__ C, int taps)
{
    __shared__ float sA[Bb_M][36];
    __shared__ float sB[Bb_K][136];
    const int K = taps * DD;
    const int row0 = blockIdx.x * Bb_M;
    const int col0 = blockIdx.y * Bb_N;
    const int tid = threadIdx.x;
    const int lane = tid & 31;
    const int wid = tid >> 5;
    const int wm = wid & 3;       // 4 warps along M (32 rows each)
    const int wn = wid >> 2;      // 2 warps along N (64 cols each)
    const int grp = lane >> 2;    // 0..7
    const int tig = lane & 3;     // 0..3

    float acc[2][8][4];
    #pragma unroll
    for (int a = 0; a < 2; a++)
        #pragma unroll
        for (int b = 0; b < 8; b++)
            #pragma unroll
            for (int c = 0; c < 4; c++) acc[a][b][c] = 0.f;

    for (int k0 = 0; k0 < K; k0 += Bb_K) {
        const int w = k0 >> 10;
        const int i0 = k0 & 1023;
        const int off = w - (taps - 1);
        // stage A (128 x 32)
        #pragma unroll
        for (int p = 0; p < 4; p++) {
            int r = (tid >> 3) + p * 32;
            int c = (tid & 7) * 4;
            int g = row0 + r;
            int t = g & (TT - 1);
            int b = g >> 11;
            int st = t + off;
            float4 v = make_float4(0.f, 0.f, 0.f, 0.f);
            if (st >= 0)
                v = *(const float4*)(A + ((size_t)(b * TT + st) * DD + i0 + c));
            *(float4*)&sA[r][c] = v;
        }
        // stage B (32 x 128)
        #pragma unroll
        for (int p = 0; p < 4; p++) {
            int kr = (tid >> 5) + p * 8;
            int c = (tid & 31) * 4;
            float4 v = *(const float4*)(Bw + (size_t)(k0 + kr) * DD + col0 + c);
            *(float4*)&sB[kr][c] = v;
        }
        __syncthreads();

        #pragma unroll
        for (int kk = 0; kk < Bb_K; kk += 8) {
            unsigned af[2][4], bf[8][2];
            #pragma unroll
            for (int mt = 0; mt < 2; mt++) {
                int r = wm * 32 + mt * 16 + grp;
                af[mt][0] = __float_as_uint(sA[r][kk + tig]);
                af[mt][1] = __float_as_uint(sA[r + 8][kk + tig]);
                af[mt][2] = __float_as_uint(sA[r][kk + tig + 4]);
                af[mt][3] = __float_as_uint(sA[r + 8][kk + tig + 4]);
            }
            #pragma unroll
            for (int nt = 0; nt < 8; nt++) {
                int cb = wn * 64 + nt * 8 + grp;
                bf[nt][0] = __float_as_uint(sB[kk + tig][cb]);
                bf[nt][1] = __float_as_uint(sB[kk + tig + 4][cb]);
            }
            #pragma unroll
            for (int mt = 0; mt < 2; mt++)
                #pragma unroll
                for (int nt = 0; nt < 8; nt++) {
                    asm volatile(
                        "mma.sync.aligned.m16n8k8.row.col.f32.tf32.tf32.f32 "
                        "{%0,%1,%2,%3}, {%4,%5,%6,%7}, {%8,%9}, {%0,%1,%2,%3};\n"
                        : "+f"(acc[mt][nt][0]), "+f"(acc[mt][nt][1]),
                          "+f"(acc[mt][nt][2]), "+f"(acc[mt][nt][3])
                        : "r"(af[mt][0]), "r"(af[mt][1]), "r"(af[mt][2]), "r"(af[mt][3]),
                          "r"(bf[nt][0]), "r"(bf[nt][1]));
                }
        }
        __syncthreads();
    }

    // epilogue
    #pragma unroll
    for (int mt = 0; mt < 2; mt++) {
        #pragma unroll
        for (int nt = 0; nt < 8; nt++) {
            int r = row0 + wm * 32 + mt * 16 + grp;
            int cc = col0 + wn * 64 + nt * 8 + tig * 2;
            float b0 = bias[cc], b1 = bias[cc + 1];
            C[(size_t)r * DD + cc]           = acc[mt][nt][0] + b0;
            C[(size_t)r * DD + cc + 1]       = acc[mt][nt][1] + b1;
            C[(size_t)(r + 8) * DD + cc]     = acc[mt][nt][2] + b0;
            C[(size_t)(r + 8) * DD + cc + 1] = acc[mt][nt][3] + b1;
        }
    }
}

// ---------------- attention ----------------
// Phase A: local window (W=16) softmax + weighted V, and the 8 log-shift raw scores.
// One warp per (b, t, h).  grid = B*T*H/8 blocks of 256 threads.
__global__ __launch_bounds__(256)
void attn_local_kernel(const float* __restrict__ q, const float* __restrict__ k,
                       const float* __restrict__ v, float* __restrict__ outb,
                       float* __restrict__ sbuf)
{
    const int gw = blockIdx.x * 8 + (threadIdx.x >> 5);
    const int lane = threadIdx.x & 31;
    const int h = gw & (HH - 1);
    const int g = gw >> 4;            // b*T + t
    const int t = g & (TT - 1);
    const int b = g >> 11;
    const float scale = 0.125f;       // 1/sqrt(64)

    const size_t base = (size_t)g * DD + h * HDIM + lane * 2;
    const float2 qv = *(const float2*)(q + base);

    float s[WW];
    #pragma unroll
    for (int w = 0; w < WW; w++) {
        int st = t + w - (WW - 1);
        float d = 0.f;
        if (st >= 0) {
            float2 kv = *(const float2*)(k + ((size_t)(b * TT + st) * DD + h * HDIM + lane * 2));
            d = qv.x * kv.x + qv.y * kv.y;
        }
        #pragma unroll
        for (int o = 16; o; o >>= 1) d += __shfl_xor_sync(0xffffffffu, d, o);
        s[w] = (st >= 0) ? d * scale : 0.f;   // zero-padded keys give exact 0 score
    }
    float m = s[0];
    #pragma unroll
    for (int w = 1; w < WW; w++) m = fmaxf(m, s[w]);
    float sum = 0.f;
    #pragma unroll
    for (int w = 0; w < WW; w++) { s[w] = __expf(s[w] - m); sum += s[w]; }
    const float inv = 1.f / sum;
    float2 accv = make_float2(0.f, 0.f);
    #pragma unroll
    for (int w = 0; w < WW; w++) {
        int st = t + w - (WW - 1);
        if (st >= 0) {
            float2 vv = *(const float2*)(v + ((size_t)(b * TT + st) * DD + h * HDIM + lane * 2));
            float a = s[w] * inv;
            accv.x += a * vv.x; accv.y += a * vv.y;
        }
    }
    *(float2*)(outb + base) = accv;

    #pragma unroll
    for (int e = 0; e < EE; e++) {
        int st = (t + (1 << e)) & (TT - 1);   // jnp.roll wraps
        float2 kv = *(const float2*)(k + ((size_t)(b * TT + st) * DD + h * HDIM + lane * 2));
        float d = qv.x * kv.x + qv.y * kv.y;
        #pragma unroll
        for (int o = 16; o; o >>= 1) d += __shfl_xor_sync(0xffffffffu, d, o);
        if (lane == 0)
            sbuf[((size_t)((b * HH + h) * EE + e)) * TT + t] = d * scale;
    }
}

// Phase B: softmax over T (2048) for each of the B*H*E = 256 rows; in-place -> alpha.
__global__ __launch_bounds__(256)
void softmax_t_kernel(float* __restrict__ s)
{
    const int row = blockIdx.x;
    const int tid = threadIdx.x;
    float* p = s + (size_t)row * TT;
    float v[8];
    float m = -1e30f;
    #pragma unroll
    for (int j = 0; j < 8; j++) { v[j] = p[tid + j * 256]; m = fmaxf(m, v[j]); }
    __shared__ float red[256];
    red[tid] = m; __syncthreads();
    for (int o = 128; o; o >>= 1) { if (tid < o) red[tid] = fmaxf(red[tid], red[tid + o]); __syncthreads(); }
    m = red[0]; __syncthreads();
    float sum = 0.f;
    #pragma unroll
    for (int j = 0; j < 8; j++) { v[j] = __expf(v[j] - m); sum += v[j]; }
    red[tid] = sum; __syncthreads();
    for (int o = 128; o; o >>= 1) { if (tid < o) red[tid] += red[tid + o]; __syncthreads(); }
    const float inv = 1.f / red[0];
    #pragma unroll
    for (int j = 0; j < 8; j++) p[tid + j * 256] = v[j] * inv;
}

// Phase C: out += sum_e alpha_e * v[(t+2^e)%T]; round to tf32 for the p-GEMM.
__global__ __launch_bounds__(256)
void attn_combine_kernel(const float* __restrict__ v, const float* __restrict__ sbuf,
                         float* __restrict__ outb)
{
    const int gw = blockIdx.x * 8 + (threadIdx.x >> 5);
    const int lane = threadIdx.x & 31;
    const int h = gw & (HH - 1);
    const int g = gw >> 4;
    const int t = g & (TT - 1);
    const int b = g >> 11;
    const size_t base = (size_t)g * DD + h * HDIM + lane * 2;
    float2 accv = *(const float2*)(outb + base);
    #pragma unroll
    for (int e = 0; e < EE; e++) {
        int st = (t + (1 << e)) & (TT - 1);
        float a = sbuf[((size_t)((b * HH + h) * EE + e)) * TT + t];
        float2 vv = *(const float2*)(v + ((size_t)(b * TT + st) * DD + h * HDIM + lane * 2));
        accv.x += a * vv.x; accv.y += a * vv.y;
    }
    accv.x = rna_tf32(accv.x);
    accv.y = rna_tf32(accv.y);
    *(float2*)(outb + base) = accv;
}

// ---------------- launch ----------------
extern "C" void kernel_launch(void* const* d_in, const int* in_sizes, int n_in,
                              void* d_out, int out_size)
{
    const float* x   = (const float*)d_in[0];
    const float* q_w = (const float*)d_in[1];
    const float* q_b = (const float*)d_in[2];
    const float* k_w = (const float*)d_in[3];
    const float* k_b = (const float*)d_in[4];
    const float* v_w = (const float*)d_in[5];
    const float* v_b = (const float*)d_in[6];
    const float* p_w = (const float*)d_in[7];
    const float* p_b = (const float*)d_in[8];
    float* out = (float*)d_out;

    float *xt, *wq, *wk, *wv, *wp, *qb, *kb, *vb, *ob, *sb;
    cudaGetSymbolAddress((void**)&xt, g_xt);
    cudaGetSymbolAddress((void**)&wq, g_wq);
    cudaGetSymbolAddress((void**)&wk, g_wk);
    cudaGetSymbolAddress((void**)&wv, g_wv);
    cudaGetSymbolAddress((void**)&wp, g_wp);
    cudaGetSymbolAddress((void**)&qb, g_q);
    cudaGetSymbolAddress((void**)&kb, g_k);
    cudaGetSymbolAddress((void**)&vb, g_v);
    cudaGetSymbolAddress((void**)&ob, g_out);
    cudaGetSymbolAddress((void**)&sb, g_s);

    // prep: tf32-round x, transpose+round weights
    round_copy_kernel<<<(MM * DD / 4 + 255) / 256, 256>>>(x, xt, MM * DD / 4);
    transpose_conv_w_kernel<<<dim3(32, 128), dim3(32, 8)>>>(q_w, wq);
    transpose_conv_w_kernel<<<dim3(32, 128), dim3(32, 8)>>>(k_w, wk);
    transpose_dense_kernel<<<dim3(32, 32), dim3(32, 8)>>>(v_w, wv);
    transpose_dense_kernel<<<dim3(32, 32), dim3(32, 8)>>>(p_w, wp);

    // projections
    dim3 ggrid(MM / Bb_M, DD / Bb_N);
    gemm_tf32_kernel<<<ggrid, 256>>>(xt, wq, q_b, qb, WW);
    gemm_tf32_kernel<<<ggrid, 256>>>(xt, wk, k_b, kb, WW);
    gemm_tf32_kernel<<<ggrid, 256>>>(xt, wv, v_b, vb, 1);

    // attention
    attn_local_kernel<<<(BB * TT * HH) / 8, 256>>>(qb, kb, vb, ob, sb);
    softmax_t_kernel<<<BB * HH * EE, 256>>>(sb);
    attn_combine_kernel<<<(BB * TT * HH) / 8, 256>>>(vb, sb, ob);

    // output projection
    gemm_tf32_kernel<<<ggrid, 256>>>(ob, wp, p_b, out, 1);
}

// round 3
// speedup vs baseline: 1.1327x; 1.1327x over previous
#include <cuda_runtime.h>
#include <cuda_bf16.h>
#include <cstdint>

// Problem constants
#define BB 2
#define TT 2048
#define DD 1024
#define HH 16
#define WW 16
#define EE 8
#define HDIM 64
#define MM (BB*TT)          // 4096 rows

// ---------------- scratch (static device arrays; no allocation) ----------------
__device__ __nv_bfloat16 g_xh[MM*DD];
__device__ __nv_bfloat16 g_xl[MM*DD];
__device__ __nv_bfloat16 g_wqh[WW*DD*DD];   // [w][i][o]  (K-major for GEMM B)
__device__ __nv_bfloat16 g_wql[WW*DD*DD];
__device__ __nv_bfloat16 g_wkh[WW*DD*DD];
__device__ __nv_bfloat16 g_wkl[WW*DD*DD];
__device__ __nv_bfloat16 g_wvh[DD*DD];      // [d][o]
__device__ __nv_bfloat16 g_wvl[DD*DD];
__device__ __nv_bfloat16 g_wph[DD*DD];
__device__ __nv_bfloat16 g_wpl[DD*DD];
__device__ float g_q[MM*DD];
__device__ float g_k[MM*DD];
__device__ float g_v[MM*DD];
__device__ float g_out[MM*DD];
__device__ __nv_bfloat16 g_oh[MM*DD];
__device__ __nv_bfloat16 g_ol[MM*DD];
__device__ float g_s[BB*HH*EE*TT];

__device__ __forceinline__ uint32_t smem_u32(const void* p) {
    uint32_t a;
    asm("{ .reg .u64 t; cvta.to.shared.u64 t, %1; cvt.u32.u64 %0, t; }" : "=r"(a) : "l"(p));
    return a;
}

// ---------------- prep: fp32 -> bf16 hi/lo split ----------------
__global__ void split_kernel(const float* __restrict__ in,
                             __nv_bfloat16* __restrict__ hi,
                             __nv_bfloat16* __restrict__ lo, int n4) {
    int i = blockIdx.x * blockDim.x + threadIdx.x;
    if (i >= n4) return;
    float4 v = ((const float4*)in)[i];
    float a[4] = {v.x, v.y, v.z, v.w};
    __nv_bfloat16 h[4], l[4];
    #pragma unroll
    for (int j = 0; j < 4; j++) {
        h[j] = __float2bfloat16(a[j]);
        l[j] = __float2bfloat16(a[j] - __bfloat162float(h[j]));
    }
    ((__nv_bfloat162*)hi)[2*i]   = __nv_bfloat162(h[0], h[1]);
    ((__nv_bfloat162*)hi)[2*i+1] = __nv_bfloat162(h[2], h[3]);
    ((__nv_bfloat162*)lo)[2*i]   = __nv_bfloat162(l[0], l[1]);
    ((__nv_bfloat162*)lo)[2*i+1] = __nv_bfloat162(l[2], l[3]);
}

// conv weight: w[o][i][t] -> hi/lo[t][i][o].  block (32,8), grid (32,128)
__global__ void split_conv_w_kernel(const float* __restrict__ w,
                                    __nv_bfloat16* __restrict__ hi,
                                    __nv_bfloat16* __restrict__ lo) {
    int o = blockIdx.x * 32 + threadIdx.x;
    int i = blockIdx.y * 8 + threadIdx.y;
    const float4* src = (const float4*)(w + ((size_t)o * DD + i) * WW);
    float vals[WW];
    #pragma unroll
    for (int p = 0; p < 4; p++) {
        float4 v = src[p];
        vals[p*4+0] = v.x; vals[p*4+1] = v.y; vals[p*4+2] = v.z; vals[p*4+3] = v.w;
    }
    #pragma unroll
    for (int t = 0; t < WW; t++) {
        size_t dst = ((size_t)t << 20) + ((size_t)i << 10) + o;
        __nv_bfloat16 h = __float2bfloat16(vals[t]);
        hi[dst] = h;
        lo[dst] = __float2bfloat16(vals[t] - __bfloat162float(h));
    }
}

// dense weight: w[o][d] -> hi/lo[d][o].  block (32,8), grid (32,32)
__global__ void split_dense_w_kernel(const float* __restrict__ w,
                                     __nv_bfloat16* __restrict__ hi,
                                     __nv_bfloat16* __restrict__ lo) {
    __shared__ float tile[32][33];
    int x = blockIdx.x * 32 + threadIdx.x;   // d
    int y0 = blockIdx.y * 32;                // o
    #pragma unroll
    for (int j = 0; j < 32; j += 8)
        tile[threadIdx.y + j][threadIdx.x] = w[(size_t)(y0 + threadIdx.y + j) * DD + x];
    __syncthreads();
    int xo = blockIdx.y * 32 + threadIdx.x;  // o
    int yo0 = blockIdx.x * 32;               // d
    #pragma unroll
    for (int j = 0; j < 32; j += 8) {
        float v = tile[threadIdx.x][threadIdx.y + j];
        __nv_bfloat16 h = __float2bfloat16(v);
        size_t dst = (size_t)(yo0 + threadIdx.y + j) * DD + xo;
        hi[dst] = h;
        lo[dst] = __float2bfloat16(v - __bfloat162float(h));
    }
}

// ---------------- bf16-split GEMM via mma.sync.m16n8k16 ----------------
// C[4096,1024] = A_shifted @ B + bias, A=[m][k] (Ah+Al), B=[k][n] (Bh+Bl, K-major).
// 3 passes: Ah*Bh, Al*Bh, Ah*Bl.  Tile 128(M)x256(N), BK=64, 8 warps (2M x 4N).
#define SAS 144                 // A smem row stride bytes (64 bf16 = 128B data)
#define SBS 528                 // B smem row stride bytes (256 bf16 = 512B data)
#define A_BYTES (128*SAS)       // 18432
#define B_BYTES (64*SBS)        // 33792
#define BUFB (A_BYTES + B_BYTES)// 52224
#define SMEM_TOTAL (2*BUFB)     // 104448

#define LDSM_X4(d0,d1,d2,d3,addr) \
    asm volatile("ldmatrix.sync.aligned.m8n8.x4.shared.b16 {%0,%1,%2,%3}, [%4];" \
        : "=r"(d0),"=r"(d1),"=r"(d2),"=r"(d3) : "r"(addr))
#define LDSM_X4T(d0,d1,d2,d3,addr) \
    asm volatile("ldmatrix.sync.aligned.m8n8.x4.trans.shared.b16 {%0,%1,%2,%3}, [%4];" \
        : "=r"(d0),"=r"(d1),"=r"(d2),"=r"(d3) : "r"(addr))
#define MMA16816(d, a0,a1,a2,a3, b0,b1) \
    asm volatile("mma.sync.aligned.m16n8k16.row.col.f32.bf16.bf16.f32 " \
        "{%0,%1,%2,%3},{%4,%5,%6,%7},{%8,%9},{%0,%1,%2,%3};" \
        : "+f"((d)[0]),"+f"((d)[1]),"+f"((d)[2]),"+f"((d)[3]) \
        : "r"(a0),"r"(a1),"r"(a2),"r"(a3),"r"(b0),"r"(b1))

__device__ __forceinline__ void stage_chunk(
    const __nv_bfloat16* Ah, const __nv_bfloat16* Al,
    const __nv_bfloat16* Bh, const __nv_bfloat16* Bl,
    int taps, int row0, int n0, int tid, int ch, uint32_t sAb, uint32_t sBb)
{
    const int per = taps * 16;
    const int pass = ch / per;
    const int rem = ch - pass * per;
    const int tap = rem >> 4;
    const int dc = rem & 15;            // k-offset = dc*64
    const __nv_bfloat16* As = (pass == 1) ? Al : Ah;
    const __nv_bfloat16* Bs = ((pass == 2) ? Bl : Bh) + ((size_t)tap << 20);
    const int off = tap - (taps - 1);

    // A: 128 rows x 64 bf16 (shifted rows, zero-fill out-of-range)
    #pragma unroll
    for (int p = 0; p < 4; p++) {
        int u = p * 256 + tid;
        int r = u >> 3;
        int cb = (u & 7) * 16;
        int gr = row0 + r;
        int t = gr & (TT - 1), bix = gr >> 11;
        int st = t + off;
        const char* src = (const char*)(As + ((size_t)((bix << 11) + st)) * DD + dc * 64) + cb;
        if (st < 0) src = (const char*)As;        // valid ptr; size 0 -> no read
        int sz = (st >= 0) ? 16 : 0;
        uint32_t dst = sAb + r * SAS + cb;
        asm volatile("cp.async.cg.shared.global [%0], [%1], 16, %2;" :: "r"(dst), "l"(src), "r"(sz));
    }
    // B: 64 k-rows x 256 bf16
    #pragma unroll
    for (int p = 0; p < 8; p++) {
        int u = p * 256 + tid;
        int kr = u >> 5;
        int cb = (u & 31) * 16;
        const char* src = (const char*)(Bs + ((size_t)(dc * 64 + kr)) * DD + n0) + cb;
        uint32_t dst = sBb + kr * SBS + cb;
        asm volatile("cp.async.cg.shared.global [%0], [%1], 16;" :: "r"(dst), "l"(src));
    }
    asm volatile("cp.async.commit_group;");
}

__global__ __launch_bounds__(256, 1)
void gemm_bf16_kernel(const __nv_bfloat16* __restrict__ Ah, const __nv_bfloat16* __restrict__ Al,
                      const __nv_bfloat16* __restrict__ Bh, const __nv_bfloat16* __restrict__ Bl,
                      const float* __restrict__ bias, float* __restrict__ C, int taps)
{
    extern __shared__ char smem[];
    const uint32_t sbase = smem_u32(smem);
    const int tid = threadIdx.x;
    const int wid = tid >> 5;
    const int lane = tid & 31;
    const int wm = wid & 1;        // 2 warps along M (64 rows each)
    const int wn = wid >> 1;       // 4 warps along N (64 cols each)
    const int row0 = blockIdx.x * 128;
    const int n0 = blockIdx.y * 256;

    float acc[4][8][4];
    #pragma unroll
    for (int a = 0; a < 4; a++)
        #pragma unroll
        for (int b = 0; b < 8; b++)
            #pragma unroll
            for (int c = 0; c < 4; c++) acc[a][b][c] = 0.f;

    const int NC = 3 * taps * 16;

    stage_chunk(Ah, Al, Bh, Bl, taps, row0, n0, tid, 0, sbase, sbase + A_BYTES);

    int buf = 0;
    for (int ch = 0; ch < NC; ch++) {
        if (ch + 1 < NC) {
            uint32_t nb = sbase + (buf ^ 1) * BUFB;
            stage_chunk(Ah, Al, Bh, Bl, taps, row0, n0, tid, ch + 1, nb, nb + A_BYTES);
            asm volatile("cp.async.wait_group 1;");
        } else {
            asm volatile("cp.async.wait_group 0;");
        }
        __syncthreads();

        const uint32_t aA = sbase + buf * BUFB;
        const uint32_t aB = aA + A_BYTES;
        #pragma unroll
        for (int kk = 0; kk < 4; kk++) {
            uint32_t a[4][4];
            #pragma unroll
            for (int mt = 0; mt < 4; mt++) {
                uint32_t addr = aA + (wm * 64 + mt * 16 + (lane & 15)) * SAS
                              + kk * 32 + (lane >> 4) * 16;
                LDSM_X4(a[mt][0], a[mt][1], a[mt][2], a[mt][3], addr);
            }
            uint32_t bf[4][4];
            #pragma unroll
            for (int nb = 0; nb < 4; nb++) {
                uint32_t addr = aB + (kk * 16 + (lane & 15)) * SBS
                              + (wn * 64 + nb * 16) * 2 + (lane >> 4) * 16;
                LDSM_X4T(bf[nb][0], bf[nb][1], bf[nb][2], bf[nb][3], addr);
            }
            #pragma unroll
            for (int mt = 0; mt < 4; mt++)
                #pragma unroll
                for (int nt = 0; nt < 8; nt++) {
                    MMA16816(acc[mt][nt], a[mt][0], a[mt][1], a[mt][2], a[mt][3],
                             bf[nt >> 1][(nt & 1) * 2], bf[nt >> 1][(nt & 1) * 2 + 1]);
                }
        }
        __syncthreads();
        buf ^= 1;
    }

    // epilogue
    #pragma unroll
    for (int mt = 0; mt < 4; mt++) {
        int row = row0 + wm * 64 + mt * 16 + (lane >> 2);
        #pragma unroll
        for (int nt = 0; nt < 8; nt++) {
            int col = n0 + wn * 64 + nt * 8 + (lane & 3) * 2;
            float2 bv = *(const float2*)(bias + col);
            float2 o0, o1;
            o0.x = acc[mt][nt][0] + bv.x; o0.y = acc[mt][nt][1] + bv.y;
            o1.x = acc[mt][nt][2] + bv.x; o1.y = acc[mt][nt][3] + bv.y;
            *(float2*)(C + (size_t)row * DD + col) = o0;
            *(float2*)(C + (size_t)(row + 8) * DD + col) = o1;
        }
    }
}

// ---------------- attention ----------------
__global__ __launch_bounds__(256)
void attn_local_kernel(const float* __restrict__ q, const float* __restrict__ k,
                       const float* __restrict__ v, float* __restrict__ outb,
                       float* __restrict__ sbuf)
{
    const int gw = blockIdx.x * 8 + (threadIdx.x >> 5);
    const int lane = threadIdx.x & 31;
    const int h = gw & (HH - 1);
    const int g = gw >> 4;            // b*T + t
    const int t = g & (TT - 1);
    const int b = g >> 11;
    const float scale = 0.125f;

    const size_t base = (size_t)g * DD + h * HDIM + lane * 2;
    const float2 qv = *(const float2*)(q + base);

    float s[WW];
    #pragma unroll
    for (int w = 0; w < WW; w++) {
        int st = t + w - (WW - 1);
        float d = 0.f;
        if (st >= 0) {
            float2 kv = *(const float2*)(k + ((size_t)(b * TT + st) * DD + h * HDIM + lane * 2));
            d = qv.x * kv.x + qv.y * kv.y;
        }
        #pragma unroll
        for (int o = 16; o; o >>= 1) d += __shfl_xor_sync(0xffffffffu, d, o);
        s[w] = (st >= 0) ? d * scale : 0.f;
    }
    float m = s[0];
    #pragma unroll
    for (int w = 1; w < WW; w++) m = fmaxf(m, s[w]);
    float sum = 0.f;
    #pragma unroll
    for (int w = 0; w < WW; w++) { s[w] = __expf(s[w] - m); sum += s[w]; }
    const float inv = 1.f / sum;
    float2 accv = make_float2(0.f, 0.f);
    #pragma unroll
    for (int w = 0; w < WW; w++) {
        int st = t + w - (WW - 1);
        if (st >= 0) {
            float2 vv = *(const float2*)(v + ((size_t)(b * TT + st) * DD + h * HDIM + lane * 2));
            float a = s[w] * inv;
            accv.x += a * vv.x; accv.y += a * vv.y;
        }
    }
    *(float2*)(outb + base) = accv;

    #pragma unroll
    for (int e = 0; e < EE; e++) {
        int st = (t + (1 << e)) & (TT - 1);
        float2 kv = *(const float2*)(k + ((size_t)(b * TT + st) * DD + h * HDIM + lane * 2));
        float d = qv.x * kv.x + qv.y * kv.y;
        #pragma unroll
        for (int o = 16; o; o >>= 1) d += __shfl_xor_sync(0xffffffffu, d, o);
        if (lane == 0)
            sbuf[((size_t)((b * HH + h) * EE + e)) * TT + t] = d * scale;
    }
}

__global__ __launch_bounds__(256)
void softmax_t_kernel(float* __restrict__ s)
{
    const int row = blockIdx.x;
    const int tid = threadIdx.x;
    float* p = s + (size_t)row * TT;
    float v[8];
    float m = -1e30f;
    #pragma unroll
    for (int j = 0; j < 8; j++) { v[j] = p[tid + j * 256]; m = fmaxf(m, v[j]); }
    __shared__ float red[256];
    red[tid] = m; __syncthreads();
    for (int o = 128; o; o >>= 1) { if (tid < o) red[tid] = fmaxf(red[tid], red[tid + o]); __syncthreads(); }
    m = red[0]; __syncthreads();
    float sum = 0.f;
    #pragma unroll
    for (int j = 0; j < 8; j++) { v[j] = __expf(v[j] - m); sum += v[j]; }
    red[tid] = sum; __syncthreads();
    for (int o = 128; o; o >>= 1) { if (tid < o) red[tid] += red[tid + o]; __syncthreads(); }
    const float inv = 1.f / red[0];
    #pragma unroll
    for (int j = 0; j < 8; j++) p[tid + j * 256] = v[j] * inv;
}

// combine: add log-shift term, split result into bf16 hi/lo for the p-GEMM
__global__ __launch_bounds__(256)
void attn_combine_kernel(const float* __restrict__ v, const float* __restrict__ sbuf,
                         const float* __restrict__ outb,
                         __nv_bfloat16* __restrict__ oh, __nv_bfloat16* __restrict__ ol)
{
    const int gw = blockIdx.x * 8 + (threadIdx.x >> 5);
    const int lane = threadIdx.x & 31;
    const int h = gw & (HH - 1);
    const int g = gw >> 4;
    const int t = g & (TT - 1);
    const int b = g >> 11;
    const size_t base = (size_t)g * DD + h * HDIM + lane * 2;
    float2 accv = *(const float2*)(outb + base);
    #pragma unroll
    for (int e = 0; e < EE; e++) {
        int st = (t + (1 << e)) & (TT - 1);
        float a = sbuf[((size_t)((b * HH + h) * EE + e)) * TT + t];
        float2 vv = *(const float2*)(v + ((size_t)(b * TT + st) * DD + h * HDIM + lane * 2));
        accv.x += a * vv.x; accv.y += a * vv.y;
    }
    __nv_bfloat16 hx = __float2bfloat16(accv.x);
    __nv_bfloat16 hy = __float2bfloat16(accv.y);
    __nv_bfloat16 lx = __float2bfloat16(accv.x - __bfloat162float(hx));
    __nv_bfloat16 ly = __float2bfloat16(accv.y - __bfloat162float(hy));
    *(__nv_bfloat162*)(oh + base) = __nv_bfloat162(hx, hy);
    *(__nv_bfloat162*)(ol + base) = __nv_bfloat162(lx, ly);
}

// ---------------- launch ----------------
extern "C" void kernel_launch(void* const* d_in, const int* in_sizes, int n_in,
                              void* d_out, int out_size)
{
    const float* x   = (const float*)d_in[0];
    const float* q_w = (const float*)d_in[1];
    const float* q_b = (const float*)d_in[2];
    const float* k_w = (const float*)d_in[3];
    const float* k_b = (const float*)d_in[4];
    const float* v_w = (const float*)d_in[5];
    const float* v_b = (const float*)d_in[6];
    const float* p_w = (const float*)d_in[7];
    const float* p_b = (const float*)d_in[8];
    float* out = (float*)d_out;

    __nv_bfloat16 *xh, *xl, *wqh, *wql, *wkh, *wkl, *wvh, *wvl, *wph, *wpl, *oh, *ol;
    float *qb, *kb, *vb, *ob, *sbuf;
    cudaGetSymbolAddress((void**)&xh, g_xh);   cudaGetSymbolAddress((void**)&xl, g_xl);
    cudaGetSymbolAddress((void**)&wqh, g_wqh); cudaGetSymbolAddress((void**)&wql, g_wql);
    cudaGetSymbolAddress((void**)&wkh, g_wkh); cudaGetSymbolAddress((void**)&wkl, g_wkl);
    cudaGetSymbolAddress((void**)&wvh, g_wvh); cudaGetSymbolAddress((void**)&wvl, g_wvl);
    cudaGetSymbolAddress((void**)&wph, g_wph); cudaGetSymbolAddress((void**)&wpl, g_wpl);
    cudaGetSymbolAddress((void**)&oh, g_oh);   cudaGetSymbolAddress((void**)&ol, g_ol);
    cudaGetSymbolAddress((void**)&qb, g_q);    cudaGetSymbolAddress((void**)&kb, g_k);
    cudaGetSymbolAddress((void**)&vb, g_v);    cudaGetSymbolAddress((void**)&ob, g_out);
    cudaGetSymbolAddress((void**)&sbuf, g_s);

    cudaFuncSetAttribute(gemm_bf16_kernel, cudaFuncAttributeMaxDynamicSharedMemorySize, SMEM_TOTAL);

    // prep: bf16 hi/lo splits (+ K-major weight transposes)
    split_kernel<<<(MM * DD / 4 + 255) / 256, 256>>>(x, xh, xl, MM * DD / 4);
    split_conv_w_kernel<<<dim3(32, 128), dim3(32, 8)>>>(q_w, wqh, wql);
    split_conv_w_kernel<<<dim3(32, 128), dim3(32, 8)>>>(k_w, wkh, wkl);
    split_dense_w_kernel<<<dim3(32, 32), dim3(32, 8)>>>(v_w, wvh, wvl);
    split_dense_w_kernel<<<dim3(32, 32), dim3(32, 8)>>>(p_w, wph, wpl);

    // projections
    dim3 ggrid(MM / 128, DD / 256);
    gemm_bf16_kernel<<<ggrid, 256, SMEM_TOTAL>>>(xh, xl, wqh, wql, q_b, qb, WW);
    gemm_bf16_kernel<<<ggrid, 256, SMEM_TOTAL>>>(xh, xl, wkh, wkl, k_b, kb, WW);
    gemm_bf16_kernel<<<ggrid, 256, SMEM_TOTAL>>>(xh, xl, wvh, wvl, v_b, vb, 1);

    // attention
    attn_local_kernel<<<(BB * TT * HH) / 8, 256>>>(qb, kb, vb, ob, sbuf);
    softmax_t_kernel<<<BB * HH * EE, 256>>>(sbuf);
    attn_combine_kernel<<<(BB * TT * HH) / 8, 256>>>(vb, sbuf, ob, oh, ol);

    // output projection
    gemm_bf16_kernel<<<ggrid, 256, SMEM_TOTAL>>>(oh, ol, wph, wpl, p_b, out, 1);
}